// round 14
// baseline (speedup 1.0000x reference)
#include <cuda_runtime.h>
#include <cstdint>
#include <cstddef>

#define NN    8192
#define FIN   256
#define FOUT  64
#define CAPS  192          // per-row shared neighbor list capacity (mean 32)
#define PROJ_BLOCKS 256
#define SCAN_BLOCKS 2048   // each owns 4 complete rows (128KB contiguous)
#define PIN_SEGS 768       // first 96MB of adj pinned in L2 via evict_last

__device__ float g_fts[(size_t)NN * FOUT];
__device__ float g_f1[NN];
__device__ float g_f2[NN];
__device__ int   g_proj_done;   // 0 at load; reset by last scan block
__device__ int   g_scan_done;

__device__ __forceinline__ float lrelu(float v) { return fmaxf(v, 0.2f * v); }

__device__ __forceinline__ unsigned long long pack2(float lo, float hi) {
    unsigned long long r;
    asm("mov.b64 %0, {%1, %2};" : "=l"(r) : "f"(lo), "f"(hi));
    return r;
}
__device__ __forceinline__ unsigned long long ffma2(unsigned long long a,
                                                    unsigned long long b,
                                                    unsigned long long c) {
    unsigned long long d;
    asm("fma.rn.f32x2 %0, %1, %2, %3;" : "=l"(d) : "l"(a), "l"(b), "l"(c));
    return d;
}
__device__ __forceinline__ float2 unpack2(unsigned long long v) {
    float2 f;
    asm("mov.b64 {%0, %1}, %2;" : "=f"(f.x), "=f"(f.y) : "l"(v));
    return f;
}

// 32B loads (required width for L2::evict_last on sm_103a)
__device__ __forceinline__ void ld32_pin(const unsigned long long* p,
                                         unsigned long long v[4]) {
    asm("ld.global.L2::evict_last.v4.u64 {%0,%1,%2,%3}, [%4];"
        : "=l"(v[0]), "=l"(v[1]), "=l"(v[2]), "=l"(v[3]) : "l"(p));
}
__device__ __forceinline__ void ld32_cs(const unsigned long long* p,
                                        unsigned long long v[4]) {
    asm("ld.global.cs.v4.u64 {%0,%1,%2,%3}, [%4];"
        : "=l"(v[0]), "=l"(v[1]), "=l"(v[2]), "=l"(v[3]) : "l"(p));
}

// Scan one 16KB half-row: 4 iters x 4-deep batches of 32B/lane (1KB/warp).
// a8 = this lane's first chunk; ubase_chunk = h*512 + lane (8-elem chunks).
template<bool PIN>
__device__ __forceinline__ void scan16k(const unsigned long long* a8,
                                        int ubase_chunk, int rl,
                                        int* s_cnt, int* s_lst)
{
#pragma unroll 1
    for (int it = 0; it < 4; ++it) {
        unsigned long long v[4][4];
#pragma unroll
        for (int k = 0; k < 4; ++k) {
            const unsigned long long* p = a8 + (size_t)(it * 4 + k) * 128;
            if (PIN) ld32_pin(p, v[k]);
            else     ld32_cs(p, v[k]);
        }
#pragma unroll
        for (int k = 0; k < 4; ++k) {
            unsigned m = 0;
#pragma unroll
            for (int i = 0; i < 4; ++i) {
                m |= (unsigned)((~v[k][i] >> 31) & 1ull) << (2 * i);
                m |= (unsigned)((~v[k][i] >> 63) & 1ull) << (2 * i + 1);
            }
            if (m) {
                const int col = (ubase_chunk + (it * 4 + k) * 32) * 8;
                int p = atomicAdd(&s_cnt[rl], __popc(m));
                while (m) {
                    const int q = __ffs(m) - 1;
                    m &= m - 1;
                    if (p < CAPS) s_lst[rl * CAPS + p] = col + q;
                    ++p;
                }
            }
        }
    }
}

// ---------------------------------------------------------------------------
// ONE kernel. Blocks [0,256): projection GEMM -> release flag.
// Blocks [256, 2304): stream 4 adj rows (2 warps/row, 16KB each, 32B/lane
// loads; first 96MB evict_last-pinned in L2) -> shared neighbor lists ->
// acquire proj -> softmax (1 warp/row) -> barrier -> gather with all 8 warps.
// ---------------------------------------------------------------------------
__global__ void __launch_bounds__(256) fused_kernel(
    const float* __restrict__ x, const float* __restrict__ W,
    const float* __restrict__ a1, const float* __restrict__ b1,
    const float* __restrict__ a2, const float* __restrict__ b2,
    const float* __restrict__ adj, const float* __restrict__ bias,
    float* __restrict__ out)
{
    __shared__ __align__(16) unsigned char sraw[12640];
    const int tid = threadIdx.x;

    if (blockIdx.x >= PROJ_BLOCKS) {
        // ==================== scan + per-row aggregate ====================
        int*   s_cnt = (int*)sraw;                         // [4]
        float* s_l   = (float*)(sraw + 16);                // [4] softmax sums
        int*   s_lst = (int*)(sraw + 32);                  // [4][CAPS]
        float* s_p   = (float*)(sraw + 32 + 4 * CAPS * 4); // [4][CAPS]

        const int seg  = blockIdx.x - PROJ_BLOCKS;
        const int r0   = seg * 4;
        const int w    = tid >> 5;        // warp 0..7
        const int lane = tid & 31;
        const int rl   = w >> 1;          // local row 0..3 (2 warps per row)
        const int h    = w & 1;           // half / role within the pair

        if (tid < 4) s_cnt[tid] = 0;
        __syncthreads();

        // u64 layout: row = 4096 u64; half-row = 2048; chunk = 4 u64 (32B)
        const unsigned long long* a8 = (const unsigned long long*)adj
            + (size_t)(r0 + rl) * 4096 + (size_t)(h * 512 + lane) * 4;
        const int ubase_chunk = h * 512 + lane;

        if (seg < PIN_SEGS) scan16k<true >(a8, ubase_chunk, rl, s_cnt, s_lst);
        else                scan16k<false>(a8, ubase_chunk, rl, s_cnt, s_lst);
        __syncthreads();                  // lists complete

        // acquire projection results
        if (tid == 0) {
            while (*(volatile int*)&g_proj_done < PROJ_BLOCKS) { }
            __threadfence();
        }
        __syncthreads();

        const int   cnt  = s_cnt[rl];
        const bool  fast = (cnt > 0 && cnt <= CAPS);
        const int   i    = r0 + rl;
        const float f1i  = g_f1[i];
        int*   lst = s_lst + rl * CAPS;
        float* pr  = s_p   + rl * CAPS;
        const int cpad = (cnt + 7) & ~7;

        // ---- softmax phase: ONE warp per row (h==0) writes smem ----
        if (fast && h == 0) {
            float mloc = -3.4e38f;
            for (int e = lane; e < cnt; e += 32) {
                const float s = lrelu(f1i + g_f2[lst[e]]);
                pr[e] = s;
                mloc = fmaxf(mloc, s);
            }
#pragma unroll
            for (int o = 16; o; o >>= 1)
                mloc = fmaxf(mloc, __shfl_xor_sync(0xffffffffu, mloc, o));
            __syncwarp();

            float l = 0.f;
            for (int e = lane; e < cpad; e += 32) {
                if (e < cnt) {
                    const float p = __expf(pr[e] - mloc);
                    pr[e] = p;
                    l += p;
                } else {
                    pr[e]  = 0.f;
                    lst[e] = 0;
                }
            }
#pragma unroll
            for (int o = 16; o; o >>= 1)
                l += __shfl_xor_sync(0xffffffffu, l, o);
            if (lane == 0) s_l[rl] = l;
        }
        __syncthreads();                  // unconditional: softmax published

        // ---- gather phase: BOTH warps of each pair, 32 features each ----
        {
            const int   f  = lane + 32 * h;
            const float bf = bias[f];

            if (fast) {
                const float l = s_l[rl];
                float A = 0.f;
                for (int e0 = 0; e0 < cpad; e0 += 8) {
#pragma unroll
                    for (int u = 0; u < 8; ++u) {
                        const float p = pr[e0 + u];
                        const int   j = lst[e0 + u];
                        A += p * g_fts[(size_t)j * FOUT + f];
                    }
                }
                const float val = A / l + bf;
                out[(size_t)i * FOUT + f] = (val > 0.f) ? val : expm1f(val);
            } else {
                // exact slow path (empty row / overflow; astronomically rare)
                const float* arow = adj + (size_t)i * NN;
                float m = -3.4e38f;
                for (int j = lane; j < NN; j += 32)
                    m = fmaxf(m, lrelu(f1i + g_f2[j]) + arow[j]);
#pragma unroll
                for (int o = 16; o; o >>= 1)
                    m = fmaxf(m, __shfl_xor_sync(0xffffffffu, m, o));

                float A = 0.f, l = 0.f;
                for (int j0 = 0; j0 < NN; j0 += 32) {
                    const float p = __expf(lrelu(f1i + g_f2[j0 + lane]) + arow[j0 + lane] - m);
                    l += p;
#pragma unroll 1
                    for (int src = 0; src < 32; ++src) {
                        const float pe = __shfl_sync(0xffffffffu, p, src);
                        if (pe > 0.f)
                            A += pe * g_fts[(size_t)(j0 + src) * FOUT + f];
                    }
                }
#pragma unroll
                for (int o = 16; o; o >>= 1)
                    l += __shfl_xor_sync(0xffffffffu, l, o);

                const float val = A / l + bf;
                out[(size_t)i * FOUT + f] = (val > 0.f) ? val : expm1f(val);
            }
        }

        // last scan block resets flags for graph replay
        __syncthreads();
        if (tid == 0) {
            const int d = atomicAdd(&g_scan_done, 1);
            if (d == SCAN_BLOCKS - 1) {
                g_proj_done = 0;
                g_scan_done = 0;
            }
        }
        return;
    }

    // ==================== proj: 32 rows x 64 cols per block ====================
    {
        float* xsT = (float*)sraw;                     // [32][34] 4352B
        float* Ws  = (float*)(sraw + 4352);            // [32][64] 8192B

        const int rowg = tid >> 4;
        const int colg = tid & 15;
        const int r0   = rowg * 2;
        const int f0   = colg * 4;
        const int rb   = blockIdx.x * 32;

        const int xrow = tid >> 3;
        const int xkq  = tid & 7;
        const float4* xg = (const float4*)(x + (size_t)(rb + xrow) * FIN) + xkq;
        const float4* W4 = (const float4*)W;
        float4* Ws4 = (float4*)Ws;

        float4 gx, gw0, gw1;
        unsigned long long acc[4];
#pragma unroll
        for (int t = 0; t < 4; ++t) acc[t] = 0ull;

        gx  = xg[0];
        gw0 = W4[tid];
        gw1 = W4[tid + 256];
        xsT[(xkq * 4 + 0) * 34 + xrow] = gx.x;
        xsT[(xkq * 4 + 1) * 34 + xrow] = gx.y;
        xsT[(xkq * 4 + 2) * 34 + xrow] = gx.z;
        xsT[(xkq * 4 + 3) * 34 + xrow] = gx.w;
        Ws4[tid]       = gw0;
        Ws4[tid + 256] = gw1;
        __syncthreads();

        for (int c = 0; c < 8; ++c) {
            if (c < 7) {
                gx  = xg[(c + 1) * 8];
                gw0 = W4[(c + 1) * 512 + tid];
                gw1 = W4[(c + 1) * 512 + tid + 256];
            }
#pragma unroll
            for (int k = 0; k < 32; ++k) {
                const float2 xv = *(const float2*)(xsT + k * 34 + r0);
                const unsigned long long xa = pack2(xv.x, xv.x);
                const unsigned long long xb = pack2(xv.y, xv.y);
                const ulonglong2 wv = *(const ulonglong2*)(Ws + k * FOUT + f0);
                acc[0] = ffma2(xa, wv.x, acc[0]);
                acc[1] = ffma2(xa, wv.y, acc[1]);
                acc[2] = ffma2(xb, wv.x, acc[2]);
                acc[3] = ffma2(xb, wv.y, acc[3]);
            }
            if (c < 7) {
                __syncthreads();
                xsT[(xkq * 4 + 0) * 34 + xrow] = gx.x;
                xsT[(xkq * 4 + 1) * 34 + xrow] = gx.y;
                xsT[(xkq * 4 + 2) * 34 + xrow] = gx.z;
                xsT[(xkq * 4 + 3) * 34 + xrow] = gx.w;
                Ws4[tid]       = gw0;
                Ws4[tid + 256] = gw1;
                __syncthreads();
            }
        }

        const int rg0 = rb + r0;
        *(ulonglong2*)(g_fts + (size_t)rg0 * FOUT + f0)       = make_ulonglong2(acc[0], acc[1]);
        *(ulonglong2*)(g_fts + (size_t)(rg0 + 1) * FOUT + f0) = make_ulonglong2(acc[2], acc[3]);

        float p1r0 = 0.f, p2r0 = 0.f, p1r1 = 0.f, p2r1 = 0.f;
#pragma unroll
        for (int t = 0; t < 2; ++t) {
            const float2 v0 = unpack2(acc[t]);
            const float2 v1 = unpack2(acc[2 + t]);
            const float a1l = a1[f0 + 2 * t], a1h = a1[f0 + 2 * t + 1];
            const float a2l = a2[f0 + 2 * t], a2h = a2[f0 + 2 * t + 1];
            p1r0 += v0.x * a1l + v0.y * a1h;
            p2r0 += v0.x * a2l + v0.y * a2h;
            p1r1 += v1.x * a1l + v1.y * a1h;
            p2r1 += v1.x * a2l + v1.y * a2h;
        }
#pragma unroll
        for (int o = 1; o < 16; o <<= 1) {
            p1r0 += __shfl_xor_sync(0xffffffffu, p1r0, o);
            p2r0 += __shfl_xor_sync(0xffffffffu, p2r0, o);
            p1r1 += __shfl_xor_sync(0xffffffffu, p1r1, o);
            p2r1 += __shfl_xor_sync(0xffffffffu, p2r1, o);
        }
        if (colg == 0) {
            g_f1[rg0]     = p1r0 + b1[0];
            g_f2[rg0]     = p2r0 + b2[0];
            g_f1[rg0 + 1] = p1r1 + b1[0];
            g_f2[rg0 + 1] = p2r1 + b2[0];
        }

        __threadfence();
        __syncthreads();
        if (tid == 0) atomicAdd(&g_proj_done, 1);
    }
}

// ---------------------------------------------------------------------------
extern "C" void kernel_launch(void* const* d_in, const int* in_sizes, int n_in,
                              void* d_out, int out_size)
{
    (void)in_sizes; (void)n_in; (void)out_size;
    const float* x    = (const float*)d_in[0];
    const float* adj  = (const float*)d_in[1];
    const float* W    = (const float*)d_in[2];
    const float* a1   = (const float*)d_in[3];
    const float* b1   = (const float*)d_in[4];
    const float* a2   = (const float*)d_in[5];
    const float* b2   = (const float*)d_in[6];
    const float* bias = (const float*)d_in[7];
    float* out = (float*)d_out;

    fused_kernel<<<PROJ_BLOCKS + SCAN_BLOCKS, 256>>>(x, W, a1, b1, a2, b2, adj, bias, out);
}

// round 15
// speedup vs baseline: 1.0565x; 1.0565x over previous
#include <cuda_runtime.h>
#include <cstdint>
#include <cstddef>

#define NN    8192
#define FIN   256
#define FOUT  64
#define CAPS  192          // per-row shared neighbor list capacity (mean 32)
#define PROJ_BLOCKS 256
#define NSEGS 2048         // 4 rows (128KB) per segment
#define SCAN_GRID 888      // persistent scan blocks (6 x 148)

__device__ float g_fts[(size_t)NN * FOUT];
__device__ float g_f1[NN];
__device__ float g_f2[NN];
__device__ int   g_proj_done;   // 0 at load; reset by last scan block
__device__ int   g_scan_done;
__device__ int   g_seg_ctr;     // work-stealing segment counter

__device__ __forceinline__ float lrelu(float v) { return fmaxf(v, 0.2f * v); }

__device__ __forceinline__ unsigned long long pack2(float lo, float hi) {
    unsigned long long r;
    asm("mov.b64 %0, {%1, %2};" : "=l"(r) : "f"(lo), "f"(hi));
    return r;
}
__device__ __forceinline__ unsigned long long ffma2(unsigned long long a,
                                                    unsigned long long b,
                                                    unsigned long long c) {
    unsigned long long d;
    asm("fma.rn.f32x2 %0, %1, %2, %3;" : "=l"(d) : "l"(a), "l"(b), "l"(c));
    return d;
}
__device__ __forceinline__ float2 unpack2(unsigned long long v) {
    float2 f;
    asm("mov.b64 {%0, %1}, %2;" : "=f"(f.x), "=f"(f.y) : "l"(v));
    return f;
}

// ---------------------------------------------------------------------------
// ONE kernel. Blocks [0,256): projection GEMM -> release flag.
// Blocks [256, 256+SCAN_GRID): PERSISTENT scan workers. Each steals segment
// ids (4 rows / 128KB) from g_seg_ctr: stream (2 warps/row, 8-deep uint4
// batches) -> shared lists -> softmax (1 warp/row) -> barrier -> gather
// (both warps, 32 feats each). No wave quantization; tails overlap streams.
// ---------------------------------------------------------------------------
__global__ void __launch_bounds__(256) fused_kernel(
    const float* __restrict__ x, const float* __restrict__ W,
    const float* __restrict__ a1, const float* __restrict__ b1,
    const float* __restrict__ a2, const float* __restrict__ b2,
    const float* __restrict__ adj, const float* __restrict__ bias,
    float* __restrict__ out)
{
    __shared__ __align__(16) unsigned char sraw[12672];
    const int tid = threadIdx.x;

    if (blockIdx.x >= PROJ_BLOCKS) {
        // ==================== persistent scan + aggregate ====================
        int*   s_cnt = (int*)sraw;                         // [4]
        float* s_l   = (float*)(sraw + 16);                // [4] softmax sums
        int*   s_hdr = (int*)(sraw + 32);                  // [seg, projok]
        int*   s_lst = (int*)(sraw + 64);                  // [4][CAPS]
        float* s_p   = (float*)(sraw + 64 + 4 * CAPS * 4); // [4][CAPS]

        const int w    = tid >> 5;        // warp 0..7
        const int lane = tid & 31;
        const int rl   = w >> 1;          // local row 0..3 (2 warps per row)
        const int h    = w & 1;           // half / role within the pair

        if (tid == 0) s_hdr[1] = 0;       // proj-not-yet-observed

#pragma unroll 1
        for (;;) {
            if (tid < 4) s_cnt[tid] = 0;
            if (tid == 0) s_hdr[0] = atomicAdd(&g_seg_ctr, 1);
            __syncthreads();
            const int seg = s_hdr[0];
            if (seg >= NSEGS) break;
            const int r0 = seg * 4;

            // ---- stream: warp covers 1024 contiguous uint4 (16KB) ----
            const uint4* a4 = (const uint4*)adj
                            + (size_t)(r0 + rl) * 2048 + h * 1024 + lane;
            const int ubase = h * 1024 + lane;

#pragma unroll 1
            for (int it = 0; it < 4; ++it) {
                uint4 v[8];
#pragma unroll
                for (int k = 0; k < 8; ++k)
                    v[k] = __ldcs(a4 + (it * 8 + k) * 32);
#pragma unroll
                for (int k = 0; k < 8; ++k) {
                    unsigned m = ((~v[k].x) >> 31)
                               | (((~v[k].y) >> 31) << 1)
                               | (((~v[k].z) >> 31) << 2)
                               | (((~v[k].w) >> 31) << 3);
                    if (m) {
                        const int col = (ubase + (it * 8 + k) * 32) * 4;
                        int p = atomicAdd(&s_cnt[rl], __popc(m));
                        while (m) {
                            const int q = __ffs(m) - 1;
                            m &= m - 1;
                            if (p < CAPS) s_lst[rl * CAPS + p] = col + q;
                            ++p;
                        }
                    }
                }
            }
            __syncthreads();              // lists complete

            // acquire projection results (one-shot per block)
            if (tid == 0 && !s_hdr[1]) {
                while (*(volatile int*)&g_proj_done < PROJ_BLOCKS) { }
                __threadfence();
                s_hdr[1] = 1;
            }
            __syncthreads();

            const int   cnt  = s_cnt[rl];
            const bool  fast = (cnt > 0 && cnt <= CAPS);
            const int   i    = r0 + rl;
            const float f1i  = g_f1[i];
            int*   lst = s_lst + rl * CAPS;
            float* pr  = s_p   + rl * CAPS;
            const int cpad = (cnt + 7) & ~7;

            // ---- softmax: ONE warp per row (h==0) writes smem ----
            if (fast && h == 0) {
                float mloc = -3.4e38f;
                for (int e = lane; e < cnt; e += 32) {
                    const float s = lrelu(f1i + g_f2[lst[e]]);
                    pr[e] = s;
                    mloc = fmaxf(mloc, s);
                }
#pragma unroll
                for (int o = 16; o; o >>= 1)
                    mloc = fmaxf(mloc, __shfl_xor_sync(0xffffffffu, mloc, o));
                __syncwarp();

                float l = 0.f;
                for (int e = lane; e < cpad; e += 32) {
                    if (e < cnt) {
                        const float p = __expf(pr[e] - mloc);
                        pr[e] = p;
                        l += p;
                    } else {
                        pr[e]  = 0.f;
                        lst[e] = 0;
                    }
                }
#pragma unroll
                for (int o = 16; o; o >>= 1)
                    l += __shfl_xor_sync(0xffffffffu, l, o);
                if (lane == 0) s_l[rl] = l;
            }
            __syncthreads();              // softmax published

            // ---- gather: BOTH warps of each pair, 32 features each ----
            {
                const int   f  = lane + 32 * h;
                const float bf = bias[f];

                if (fast) {
                    const float l = s_l[rl];
                    float A = 0.f;
                    for (int e0 = 0; e0 < cpad; e0 += 8) {
#pragma unroll
                        for (int u = 0; u < 8; ++u) {
                            const float p = pr[e0 + u];
                            const int   j = lst[e0 + u];
                            A += p * g_fts[(size_t)j * FOUT + f];
                        }
                    }
                    const float val = A / l + bf;
                    out[(size_t)i * FOUT + f] = (val > 0.f) ? val : expm1f(val);
                } else {
                    // exact slow path (empty row / overflow; astronomically rare)
                    const float* arow = adj + (size_t)i * NN;
                    float m = -3.4e38f;
                    for (int j = lane; j < NN; j += 32)
                        m = fmaxf(m, lrelu(f1i + g_f2[j]) + arow[j]);
#pragma unroll
                    for (int o = 16; o; o >>= 1)
                        m = fmaxf(m, __shfl_xor_sync(0xffffffffu, m, o));

                    float A = 0.f, l = 0.f;
                    for (int j0 = 0; j0 < NN; j0 += 32) {
                        const float p = __expf(lrelu(f1i + g_f2[j0 + lane]) + arow[j0 + lane] - m);
                        l += p;
#pragma unroll 1
                        for (int src = 0; src < 32; ++src) {
                            const float pe = __shfl_sync(0xffffffffu, p, src);
                            if (pe > 0.f)
                                A += pe * g_fts[(size_t)(j0 + src) * FOUT + f];
                        }
                    }
#pragma unroll
                    for (int o = 16; o; o >>= 1)
                        l += __shfl_xor_sync(0xffffffffu, l, o);

                    const float val = A / l + bf;
                    out[(size_t)i * FOUT + f] = (val > 0.f) ? val : expm1f(val);
                }
            }
            __syncthreads();              // before resetting s_cnt next iter
        }

        // last scan block resets all flags for graph replay
        if (tid == 0) {
            const int d = atomicAdd(&g_scan_done, 1);
            if (d == SCAN_GRID - 1) {
                g_proj_done = 0;
                g_scan_done = 0;
                g_seg_ctr   = 0;
            }
        }
        return;
    }

    // ==================== proj: 32 rows x 64 cols per block ====================
    {
        float* xsT = (float*)sraw;                     // [32][34] 4352B
        float* Ws  = (float*)(sraw + 4352);            // [32][64] 8192B

        const int rowg = tid >> 4;
        const int colg = tid & 15;
        const int r0   = rowg * 2;
        const int f0   = colg * 4;
        const int rb   = blockIdx.x * 32;

        const int xrow = tid >> 3;
        const int xkq  = tid & 7;
        const float4* xg = (const float4*)(x + (size_t)(rb + xrow) * FIN) + xkq;
        const float4* W4 = (const float4*)W;
        float4* Ws4 = (float4*)Ws;

        float4 gx, gw0, gw1;
        unsigned long long acc[4];
#pragma unroll
        for (int t = 0; t < 4; ++t) acc[t] = 0ull;

        gx  = xg[0];
        gw0 = W4[tid];
        gw1 = W4[tid + 256];
        xsT[(xkq * 4 + 0) * 34 + xrow] = gx.x;
        xsT[(xkq * 4 + 1) * 34 + xrow] = gx.y;
        xsT[(xkq * 4 + 2) * 34 + xrow] = gx.z;
        xsT[(xkq * 4 + 3) * 34 + xrow] = gx.w;
        Ws4[tid]       = gw0;
        Ws4[tid + 256] = gw1;
        __syncthreads();

        for (int c = 0; c < 8; ++c) {
            if (c < 7) {
                gx  = xg[(c + 1) * 8];
                gw0 = W4[(c + 1) * 512 + tid];
                gw1 = W4[(c + 1) * 512 + tid + 256];
            }
#pragma unroll
            for (int k = 0; k < 32; ++k) {
                const float2 xv = *(const float2*)(xsT + k * 34 + r0);
                const unsigned long long xa = pack2(xv.x, xv.x);
                const unsigned long long xb = pack2(xv.y, xv.y);
                const ulonglong2 wv = *(const ulonglong2*)(Ws + k * FOUT + f0);
                acc[0] = ffma2(xa, wv.x, acc[0]);
                acc[1] = ffma2(xa, wv.y, acc[1]);
                acc[2] = ffma2(xb, wv.x, acc[2]);
                acc[3] = ffma2(xb, wv.y, acc[3]);
            }
            if (c < 7) {
                __syncthreads();
                xsT[(xkq * 4 + 0) * 34 + xrow] = gx.x;
                xsT[(xkq * 4 + 1) * 34 + xrow] = gx.y;
                xsT[(xkq * 4 + 2) * 34 + xrow] = gx.z;
                xsT[(xkq * 4 + 3) * 34 + xrow] = gx.w;
                Ws4[tid]       = gw0;
                Ws4[tid + 256] = gw1;
                __syncthreads();
            }
        }

        const int rg0 = rb + r0;
        *(ulonglong2*)(g_fts + (size_t)rg0 * FOUT + f0)       = make_ulonglong2(acc[0], acc[1]);
        *(ulonglong2*)(g_fts + (size_t)(rg0 + 1) * FOUT + f0) = make_ulonglong2(acc[2], acc[3]);

        float p1r0 = 0.f, p2r0 = 0.f, p1r1 = 0.f, p2r1 = 0.f;
#pragma unroll
        for (int t = 0; t < 2; ++t) {
            const float2 v0 = unpack2(acc[t]);
            const float2 v1 = unpack2(acc[2 + t]);
            const float a1l = a1[f0 + 2 * t], a1h = a1[f0 + 2 * t + 1];
            const float a2l = a2[f0 + 2 * t], a2h = a2[f0 + 2 * t + 1];
            p1r0 += v0.x * a1l + v0.y * a1h;
            p2r0 += v0.x * a2l + v0.y * a2h;
            p1r1 += v1.x * a1l + v1.y * a1h;
            p2r1 += v1.x * a2l + v1.y * a2h;
        }
#pragma unroll
        for (int o = 1; o < 16; o <<= 1) {
            p1r0 += __shfl_xor_sync(0xffffffffu, p1r0, o);
            p2r0 += __shfl_xor_sync(0xffffffffu, p2r0, o);
            p1r1 += __shfl_xor_sync(0xffffffffu, p1r1, o);
            p2r1 += __shfl_xor_sync(0xffffffffu, p2r1, o);
        }
        if (colg == 0) {
            g_f1[rg0]     = p1r0 + b1[0];
            g_f2[rg0]     = p2r0 + b2[0];
            g_f1[rg0 + 1] = p1r1 + b1[0];
            g_f2[rg0 + 1] = p2r1 + b2[0];
        }

        __threadfence();
        __syncthreads();
        if (tid == 0) atomicAdd(&g_proj_done, 1);
    }
}

// ---------------------------------------------------------------------------
extern "C" void kernel_launch(void* const* d_in, const int* in_sizes, int n_in,
                              void* d_out, int out_size)
{
    (void)in_sizes; (void)n_in; (void)out_size;
    const float* x    = (const float*)d_in[0];
    const float* adj  = (const float*)d_in[1];
    const float* W    = (const float*)d_in[2];
    const float* a1   = (const float*)d_in[3];
    const float* b1   = (const float*)d_in[4];
    const float* a2   = (const float*)d_in[5];
    const float* b2   = (const float*)d_in[6];
    const float* bias = (const float*)d_in[7];
    float* out = (float*)d_out;

    fused_kernel<<<PROJ_BLOCKS + SCAN_GRID, 256>>>(x, W, a1, b1, a2, b2, adj, bias, out);
}